// round 2
// baseline (speedup 1.0000x reference)
#include <cuda_runtime.h>

// LocalAttention: 7x7 windowed MHA + depthwise-3x3 LePE on V.
// B=16, H=W=112, DIM=384, HEADS=12, head_dim=32, windows=16x16 per image.
// One block per (window, head): grid (4096, 12), 64 threads (8 ti x 8 tj).
// fp32 compute via packed fma.rn.f32x2 (2 MACs/issue on sm_103a).

typedef unsigned long long u64;

#define QKS 52   // qT/kT row stride (floats), even -> 8B aligned u64 loads
#define VS  36   // v row stride
#define SS  50   // score row stride

__device__ __forceinline__ u64 pack2(float lo, float hi) {
    u64 r; asm("mov.b64 %0, {%1, %2};" : "=l"(r) : "f"(lo), "f"(hi)); return r;
}
__device__ __forceinline__ void unpack2(u64 v, float &lo, float &hi) {
    asm("mov.b64 {%0, %1}, %2;" : "=f"(lo), "=f"(hi) : "l"(v));
}
__device__ __forceinline__ u64 ffma2(u64 a, u64 b, u64 c) {
    u64 d; asm("fma.rn.f32x2 %0, %1, %2, %3;" : "=l"(d) : "l"(a), "l"(b), "l"(c));
    return d;
}

__global__ __launch_bounds__(64)
void la_kernel(const float* __restrict__ qkv,
               const float* __restrict__ cw,
               const float* __restrict__ cb,
               float* __restrict__ out)
{
    // smem layout (floats), all sub-offsets multiple of 4 floats (16B aligned)
    __shared__ __align__(16) float sm[8276];
    float* qT  = sm;            // [32][QKS]  q^T, scaled
    float* kT  = sm + 1664;     // [32][QKS]  k^T
    float* vsm = sm + 3328;     // [49][VS]   v, token-major
    float* S   = sm + 5092;     // [56][SS]   scores -> exp(scores)
    float* wsm = sm + 7892;     // [9][32]    depthwise conv weights (tap-major)
    float* bsm = sm + 8180;     // [32]       conv bias
    float* rsm = sm + 8212;     // [49]       1/rowsum

    const int tid = threadIdx.x;
    const int h   = blockIdx.y;
    const int win = blockIdx.x;
    const int b   = win >> 8;
    const int wy  = (win >> 4) & 15;
    const int wx  = win & 15;
    const int tok0  = b * 12544 + wy * 784 + wx * 7;  // global token of window (0,0)
    const int cbase = h * 32;

    const float scale = 0.17677669529663687f;  // 1/sqrt(32)
    const size_t koff = 77070336ull;            // B*L*DIM = 16*12544*384

    // ---- load q,k,v window (49 tokens x 32 ch), transpose q/k ----
    for (int idx = tid; idx < 1568; idx += 64) {
        int tok = idx >> 5, d = idx & 31;
        int ly = tok / 7, lx = tok - ly * 7;
        size_t g = (size_t)(tok0 + ly * 112 + lx) * 384 + cbase + d;
        qT[d * QKS + tok] = qkv[g] * scale;
        kT[d * QKS + tok] = qkv[g + koff];
        vsm[tok * VS + d] = qkv[g + 2 * koff];
    }
    for (int idx = tid; idx < 288; idx += 64) {
        int tap = idx >> 5, d = idx & 31;
        wsm[tap * 32 + d] = cw[(cbase + d) * 9 + tap];
    }
    if (tid < 32) bsm[tid] = cb[cbase + tid];
    __syncthreads();

    const int ti = tid >> 3;   // 0..7 -> query rows ti*7 .. ti*7+6 (ti==7 pad)
    const int tj = tid & 7;    // 0..7 -> key cols  tj*8 .. tj*8+7 (some pad)

    // ---- phase 1: S = (q*scale) @ k^T  (49x49, padded 56x64) ----
    {
        u64 acc[7][4];
        #pragma unroll
        for (int r = 0; r < 7; r++)
            #pragma unroll
            for (int p = 0; p < 4; p++) acc[r][p] = 0ull;

        const float* qb = qT + ti * 7;
        const float* kb = kT + tj * 8;
        #pragma unroll 4
        for (int d = 0; d < 32; d++) {
            const float* kr = kb + d * QKS;
            u64 k0 = *(const u64*)(kr);
            u64 k1 = *(const u64*)(kr + 2);
            u64 k2 = *(const u64*)(kr + 4);
            u64 k3 = *(const u64*)(kr + 6);
            const float* qr = qb + d * QKS;
            #pragma unroll
            for (int r = 0; r < 7; r++) {
                u64 q2 = pack2(qr[r], qr[r]);
                acc[r][0] = ffma2(q2, k0, acc[r][0]);
                acc[r][1] = ffma2(q2, k1, acc[r][1]);
                acc[r][2] = ffma2(q2, k2, acc[r][2]);
                acc[r][3] = ffma2(q2, k3, acc[r][3]);
            }
        }
        if (ti < 7) {
            #pragma unroll
            for (int r = 0; r < 7; r++) {
                float* srow = S + (ti * 7 + r) * SS + tj * 8;
                #pragma unroll
                for (int p = 0; p < 4; p++) {
                    float lo, hi; unpack2(acc[r][p], lo, hi);
                    int j = tj * 8 + 2 * p;
                    if (j     < 49) srow[2 * p]     = lo;
                    if (j + 1 < 49) srow[2 * p + 1] = hi;
                }
            }
        }
    }
    __syncthreads();

    // ---- softmax rows: store exp(s - max), keep 1/sum (defer normalization) ----
    if (tid < 49) {
        float* row = S + tid * SS;
        float m = -1e30f;
        #pragma unroll 7
        for (int j = 0; j < 49; j++) m = fmaxf(m, row[j]);
        float s = 0.f;
        #pragma unroll 7
        for (int j = 0; j < 49; j++) {
            float e = __expf(row[j] - m);
            row[j] = e;
            s += e;
        }
        rsm[tid] = 1.f / s;
    }
    __syncthreads();

    // ---- phase 2: out = softmax(S) @ V + LePE(V) ----
    {
        u64 att[7][2], lep[7][2];
        float4 bb = *(const float4*)(bsm + tj * 4);
        u64 b01 = pack2(bb.x, bb.y), b23 = pack2(bb.z, bb.w);
        #pragma unroll
        for (int r = 0; r < 7; r++) {
            att[r][0] = 0ull; att[r][1] = 0ull;
            lep[r][0] = b01;  lep[r][1] = b23;
        }

        // LePE: output pixel (y=ti, x=r), depthwise 3x3, zero pad inside window
        #pragma unroll
        for (int ky = 0; ky < 3; ky++) {
            int ny = ti + ky - 1;
            if (ny >= 0 && ny <= 6) {
                #pragma unroll
                for (int kx = 0; kx < 3; kx++) {
                    const float* wp = wsm + (ky * 3 + kx) * 32 + tj * 4;
                    u64 w0 = *(const u64*)wp, w1 = *(const u64*)(wp + 2);
                    #pragma unroll
                    for (int r = 0; r < 7; r++) {
                        int nx = r + kx - 1;
                        if (nx >= 0 && nx <= 6) {
                            const float* vp = vsm + (ny * 7 + nx) * VS + tj * 4;
                            u64 v0 = *(const u64*)vp, v1 = *(const u64*)(vp + 2);
                            lep[r][0] = ffma2(w0, v0, lep[r][0]);
                            lep[r][1] = ffma2(w1, v1, lep[r][1]);
                        }
                    }
                }
            }
        }

        // attention accumulation: att[i][d] = sum_k expS[i][k] * V[k][d]
        const float* Sb = S + (ti * 7) * SS;
        #pragma unroll 7
        for (int k = 0; k < 49; k++) {
            const float* vp = vsm + k * VS + tj * 4;
            u64 v0 = *(const u64*)vp, v1 = *(const u64*)(vp + 2);
            #pragma unroll
            for (int r = 0; r < 7; r++) {
                float p = Sb[r * SS + k];
                u64 p2 = pack2(p, p);
                att[r][0] = ffma2(p2, v0, att[r][0]);
                att[r][1] = ffma2(p2, v1, att[r][1]);
            }
        }

        if (ti < 7) {
            #pragma unroll
            for (int r = 0; r < 7; r++) {
                int i = ti * 7 + r;
                float inv = rsm[i];
                float a0, a1, a2, a3, l0, l1, l2, l3;
                unpack2(att[r][0], a0, a1); unpack2(att[r][1], a2, a3);
                unpack2(lep[r][0], l0, l1); unpack2(lep[r][1], l2, l3);
                float4 o;
                o.x = a0 * inv + l0;
                o.y = a1 * inv + l1;
                o.z = a2 * inv + l2;
                o.w = a3 * inv + l3;
                *(float4*)(out + (size_t)(tok0 + ti * 112 + r) * 384 + cbase + tj * 4) = o;
            }
        }
    }
}

extern "C" void kernel_launch(void* const* d_in, const int* in_sizes, int n_in,
                              void* d_out, int out_size)
{
    const float* qkv = (const float*)d_in[0];
    const float* cw  = (const float*)d_in[1];
    const float* cb  = (const float*)d_in[2];
    float* o = (float*)d_out;
    dim3 grid(4096, 12, 1);
    la_kernel<<<grid, 64>>>(qkv, cw, cb, o);
}

// round 3
// speedup vs baseline: 1.1786x; 1.1786x over previous
#include <cuda_runtime.h>

// LocalAttention: 7x7 windowed MHA + depthwise-3x3 LePE on V.
// One block per (window, head): grid (4096, 12), 64 threads (8 ti x 8 tj).
// fp32 via packed fma.rn.f32x2. Phase-1 k columns remapped to 4tj+{0..3},
// 4tj+32+{0..3} so k loads are conflict-free LDS.128. S aliases qT/kT.

typedef unsigned long long u64;

#define QS 52   // qT row stride
#define KS 64   // kT row stride (cols 0..63, 49..63 zero pad)
#define VS 36   // v row stride
#define SS 50   // score row stride (49 rows)

__device__ __forceinline__ u64 pack2(float lo, float hi) {
    u64 r; asm("mov.b64 %0, {%1, %2};" : "=l"(r) : "f"(lo), "f"(hi)); return r;
}
__device__ __forceinline__ void unpack2(u64 v, float &lo, float &hi) {
    asm("mov.b64 {%0, %1}, %2;" : "=f"(lo), "=f"(hi) : "l"(v));
}
__device__ __forceinline__ u64 ffma2(u64 a, u64 b, u64 c) {
    u64 d; asm("fma.rn.f32x2 %0, %1, %2, %3;" : "=l"(d) : "l"(a), "l"(b), "l"(c));
    return d;
}

__global__ __launch_bounds__(64)
void la_kernel(const float* __restrict__ qkv,
               const float* __restrict__ cw,
               const float* __restrict__ cb,
               float* __restrict__ out)
{
    // floats: [0,3712) = union{ qT[32*52]+kT[32*64] | S[49*50] }
    __shared__ __align__(16) float sm[5848];
    float* qT  = sm;            // [32][QS]
    float* kT  = sm + 1664;     // [32][KS]
    float* S   = sm;            // [49][SS]  (aliases qT/kT after phase 1)
    float* vsm = sm + 3712;     // [49][VS]
    float* wsm = sm + 5476;     // [9][32]
    float* bsm = sm + 5764;     // [32]
    float* rsm = sm + 5796;     // [49] 1/rowsum

    const int tid = threadIdx.x;
    const int h   = blockIdx.y;
    const int win = blockIdx.x;
    const int b   = win >> 8;
    const int wy  = (win >> 4) & 15;
    const int wx  = win & 15;
    const int tok0  = b * 12544 + wy * 784 + wx * 7;
    const int cbase = h * 32;

    const float scale = 0.17677669529663687f;  // 1/sqrt(32)
    const size_t koff4 = 19267584ull;           // B*L*DIM/4 (float4 units)

    // zero kT pad cols 49..63 (read by phase 1, never written by loader)
    for (int i = tid; i < 480; i += 64) {
        int d = i / 15;
        kT[d * KS + 49 + (i - d * 15)] = 0.f;
    }

    // ---- vectorized load: 49 tokens x 8 float4 per array ----
    const float4* qkv4 = (const float4*)qkv;
    for (int idx = tid; idx < 392; idx += 64) {
        int tok = idx >> 3, w = idx & 7;        // w = float4 index (d = 4w..4w+3)
        int ly = tok / 7, lx = tok - ly * 7;
        size_t g = (size_t)(tok0 + ly * 112 + lx) * 96 + h * 8 + w;
        float4 q4 = qkv4[g];
        float4 k4 = qkv4[g + koff4];
        float4 v4 = qkv4[g + 2 * koff4];
        int d0 = 4 * w;
        qT[(d0    ) * QS + tok] = q4.x * scale;
        qT[(d0 + 1) * QS + tok] = q4.y * scale;
        qT[(d0 + 2) * QS + tok] = q4.z * scale;
        qT[(d0 + 3) * QS + tok] = q4.w * scale;
        kT[(d0    ) * KS + tok] = k4.x;
        kT[(d0 + 1) * KS + tok] = k4.y;
        kT[(d0 + 2) * KS + tok] = k4.z;
        kT[(d0 + 3) * KS + tok] = k4.w;
        *(float4*)(vsm + tok * VS + d0) = v4;
    }
    for (int idx = tid; idx < 288; idx += 64) {
        int tap = idx >> 5, d = idx & 31;
        wsm[tap * 32 + d] = cw[(cbase + d) * 9 + tap];
    }
    if (tid < 32) bsm[tid] = cb[cbase + tid];
    __syncthreads();

    const int ti = tid >> 3;   // 0..7 (7 query rows each; ti==7 pad)
    const int tj = tid & 7;    // key cols 4tj+{0..3} and 4tj+32+{0..3}

    // ---- phase 1: S = q @ k^T (acc kept in regs across the alias sync) ----
    u64 acc[7][4];
    #pragma unroll
    for (int r = 0; r < 7; r++)
        #pragma unroll
        for (int p = 0; p < 4; p++) acc[r][p] = 0ull;

    {
        const float* qb = qT + ti * 7;
        const float* kb = kT + (tj << 2);
        #pragma unroll 8
        for (int d = 0; d < 32; d++) {
            const float* kr = kb + d * KS;
            ulonglong2 ka = *(const ulonglong2*)(kr);       // cols 4tj..4tj+3
            ulonglong2 kc = *(const ulonglong2*)(kr + 32);  // cols 4tj+32..35
            const float* qr = qb + d * QS;
            #pragma unroll
            for (int r = 0; r < 7; r++) {
                u64 q2 = pack2(qr[r], qr[r]);
                acc[r][0] = ffma2(q2, ka.x, acc[r][0]);
                acc[r][1] = ffma2(q2, ka.y, acc[r][1]);
                acc[r][2] = ffma2(q2, kc.x, acc[r][2]);
                acc[r][3] = ffma2(q2, kc.y, acc[r][3]);
            }
        }
    }
    __syncthreads();   // all qT/kT reads done; S may now overwrite them

    if (ti < 7) {
        const int c1 = 4 * tj + 32;
        #pragma unroll
        for (int r = 0; r < 7; r++) {
            float* srow = S + (ti * 7 + r) * SS;
            *(u64*)(srow + 4 * tj)     = acc[r][0];   // cols < 32: always valid
            *(u64*)(srow + 4 * tj + 2) = acc[r][1];
            float lo, hi;
            unpack2(acc[r][2], lo, hi);
            if (c1     < 49) srow[c1]     = lo;
            if (c1 + 1 < 49) srow[c1 + 1] = hi;
            unpack2(acc[r][3], lo, hi);
            if (c1 + 2 < 49) srow[c1 + 2] = lo;
            if (c1 + 3 < 49) srow[c1 + 3] = hi;
        }
    }
    __syncthreads();

    // ---- softmax rows: store exp(s - max), keep 1/sum ----
    if (tid < 49) {
        float* row = S + tid * SS;
        float m = -1e30f;
        #pragma unroll 7
        for (int j = 0; j < 49; j++) m = fmaxf(m, row[j]);
        float s = 0.f;
        #pragma unroll 7
        for (int j = 0; j < 49; j++) {
            float e = __expf(row[j] - m);
            row[j] = e;
            s += e;
        }
        rsm[tid] = 1.f / s;
    }
    __syncthreads();

    // ---- phase 2: out = softmax(S) @ V + LePE(V) ----
    {
        u64 att[7][2], lep[7][2];
        float4 bb = *(const float4*)(bsm + tj * 4);
        u64 b01 = pack2(bb.x, bb.y), b23 = pack2(bb.z, bb.w);
        #pragma unroll
        for (int r = 0; r < 7; r++) {
            att[r][0] = 0ull; att[r][1] = 0ull;
            lep[r][0] = b01;  lep[r][1] = b23;
        }

        // LePE: output pixel (y=ti, x=r)
        #pragma unroll
        for (int ky = 0; ky < 3; ky++) {
            int ny = ti + ky - 1;
            if (ny >= 0 && ny <= 6) {
                #pragma unroll
                for (int kx = 0; kx < 3; kx++) {
                    const ulonglong2 w2 =
                        *(const ulonglong2*)(wsm + (ky * 3 + kx) * 32 + tj * 4);
                    #pragma unroll
                    for (int r = 0; r < 7; r++) {
                        int nx = r + kx - 1;
                        if (nx >= 0 && nx <= 6) {
                            ulonglong2 v2 =
                                *(const ulonglong2*)(vsm + (ny * 7 + nx) * VS + tj * 4);
                            lep[r][0] = ffma2(w2.x, v2.x, lep[r][0]);
                            lep[r][1] = ffma2(w2.y, v2.y, lep[r][1]);
                        }
                    }
                }
            }
        }

        // att[i][:] = sum_k expS[i][k] * V[k][:]
        const float* Sb = S + (ti * 7) * SS;
        #pragma unroll 7
        for (int k = 0; k < 49; k++) {
            ulonglong2 v2 = *(const ulonglong2*)(vsm + k * VS + (tj << 2));
            #pragma unroll
            for (int r = 0; r < 7; r++) {
                float p = Sb[r * SS + k];
                u64 p2 = pack2(p, p);
                att[r][0] = ffma2(p2, v2.x, att[r][0]);
                att[r][1] = ffma2(p2, v2.y, att[r][1]);
            }
        }

        if (ti < 7) {
            #pragma unroll
            for (int r = 0; r < 7; r++) {
                float inv = rsm[ti * 7 + r];
                float a0, a1, a2, a3, l0, l1, l2, l3;
                unpack2(att[r][0], a0, a1); unpack2(att[r][1], a2, a3);
                unpack2(lep[r][0], l0, l1); unpack2(lep[r][1], l2, l3);
                float4 o;
                o.x = a0 * inv + l0;
                o.y = a1 * inv + l1;
                o.z = a2 * inv + l2;
                o.w = a3 * inv + l3;
                *(float4*)(out + (size_t)(tok0 + ti * 112 + r) * 384 + cbase + tj * 4) = o;
            }
        }
    }
}

extern "C" void kernel_launch(void* const* d_in, const int* in_sizes, int n_in,
                              void* d_out, int out_size)
{
    const float* qkv = (const float*)d_in[0];
    const float* cw  = (const float*)d_in[1];
    const float* cb  = (const float*)d_in[2];
    float* o = (float*)d_out;
    dim3 grid(4096, 12, 1);
    la_kernel<<<grid, 64>>>(qkv, cw, cb, o);
}

// round 4
// speedup vs baseline: 1.2963x; 1.0999x over previous
#include <cuda_runtime.h>

// LocalAttention: 7x7 windowed MHA + depthwise-3x3 LePE on V.
// grid (4096, 12), 64 threads (8 ti x 8 tj). fp32 via fma.rn.f32x2.
// R3: register softmax (shfl), float4 S reads in phase 2, float4 q in phase 1.

typedef unsigned long long u64;

#define QVS 36   // q / v token-major row stride
#define KS  64   // kT row stride (cols 49..63 zero)
#define SS  52   // expS row stride (cols 49..51 zero)

__device__ __forceinline__ u64 pack2(float lo, float hi) {
    u64 r; asm("mov.b64 %0, {%1, %2};" : "=l"(r) : "f"(lo), "f"(hi)); return r;
}
__device__ __forceinline__ void unpack2(u64 v, float &lo, float &hi) {
    asm("mov.b64 {%0, %1}, %2;" : "=f"(lo), "=f"(hi) : "l"(v));
}
__device__ __forceinline__ u64 ffma2(u64 a, u64 b, u64 c) {
    u64 d; asm("fma.rn.f32x2 %0, %1, %2, %3;" : "=l"(d) : "l"(a), "l"(b), "l"(c));
    return d;
}

__global__ __launch_bounds__(64, 8)
void la_kernel(const float* __restrict__ qkv,
               const float* __restrict__ cw,
               const float* __restrict__ cb,
               float* __restrict__ out)
{
    // floats: [0,4064) = union{ qsm[56*36]+kT[32*64] | S[49*52] }
    __shared__ __align__(16) float sm[6256];
    float* qsm = sm;            // [56][QVS] token-major (rows 49..55 garbage pad)
    float* kT  = sm + 2016;     // [32][KS]
    float* S   = sm;            // [49][SS]  aliases qsm/kT after phase 1
    float* vsm = sm + 4064;     // [52][QVS] rows 49..51 zero
    float* wsm = sm + 5936;     // [9][32]
    float* bsm = sm + 6224;     // [32]

    const int tid = threadIdx.x;
    const int h   = blockIdx.y;
    const int win = blockIdx.x;
    const int b   = win >> 8;
    const int wy  = (win >> 4) & 15;
    const int wx  = win & 15;
    const int tok0  = b * 12544 + wy * 784 + wx * 7;
    const int cbase = h * 32;

    const float scale = 0.17677669529663687f;  // 1/sqrt(32)
    const size_t koff4 = 19267584ull;           // B*L*DIM/4 (float4 units)

    // zero kT pad cols 49..63
    for (int i = tid; i < 480; i += 64) {
        int d = i / 15;
        kT[d * KS + 49 + (i - d * 15)] = 0.f;
    }
    // zero v pad rows 49..51
    for (int i = tid; i < 108; i += 64) vsm[1764 + i] = 0.f;

    // ---- vectorized load ----
    const float4* qkv4 = (const float4*)qkv;
    for (int idx = tid; idx < 392; idx += 64) {
        int tok = idx >> 3, w = idx & 7;        // d = 4w..4w+3
        int ly = tok / 7, lx = tok - ly * 7;
        size_t g = (size_t)(tok0 + ly * 112 + lx) * 96 + h * 8 + w;
        float4 q4 = qkv4[g];
        float4 k4 = qkv4[g + koff4];
        float4 v4 = qkv4[g + 2 * koff4];
        int d0 = 4 * w;
        q4.x *= scale; q4.y *= scale; q4.z *= scale; q4.w *= scale;
        *(float4*)(qsm + tok * QVS + d0) = q4;
        kT[(d0    ) * KS + tok] = k4.x;
        kT[(d0 + 1) * KS + tok] = k4.y;
        kT[(d0 + 2) * KS + tok] = k4.z;
        kT[(d0 + 3) * KS + tok] = k4.w;
        *(float4*)(vsm + tok * QVS + d0) = v4;
    }
    for (int idx = tid; idx < 288; idx += 64) {
        int tap = idx >> 5, d = idx & 31;
        wsm[tap * 32 + d] = cw[(cbase + d) * 9 + tap];
    }
    if (tid < 32) bsm[tid] = cb[cbase + tid];
    __syncthreads();

    const int ti = tid >> 3;   // 0..7 (rows 7ti..7ti+6; ti==7 pad lane)
    const int tj = tid & 7;    // cols 4tj+{0..3}, 4tj+32+{0..3}

    // ---- phase 1: S = q @ k^T, acc in regs ----
    u64 acc[7][4];
    #pragma unroll
    for (int r = 0; r < 7; r++)
        #pragma unroll
        for (int p = 0; p < 4; p++) acc[r][p] = 0ull;

    {
        const float* qb = qsm + (7 * ti) * QVS;
        const float* kb = kT + (tj << 2);
        #pragma unroll
        for (int dg = 0; dg < 8; dg++) {
            float4 q4[7];
            #pragma unroll
            for (int r = 0; r < 7; r++)
                q4[r] = *(const float4*)(qb + r * QVS + 4 * dg);
            #pragma unroll
            for (int dd = 0; dd < 4; dd++) {
                const float* kr = kb + (4 * dg + dd) * KS;
                ulonglong2 ka = *(const ulonglong2*)(kr);
                ulonglong2 kc = *(const ulonglong2*)(kr + 32);
                #pragma unroll
                for (int r = 0; r < 7; r++) {
                    float qv = (dd == 0) ? q4[r].x : (dd == 1) ? q4[r].y
                             : (dd == 2) ? q4[r].z : q4[r].w;
                    u64 q2 = pack2(qv, qv);
                    acc[r][0] = ffma2(q2, ka.x, acc[r][0]);
                    acc[r][1] = ffma2(q2, ka.y, acc[r][1]);
                    acc[r][2] = ffma2(q2, kc.x, acc[r][2]);
                    acc[r][3] = ffma2(q2, kc.y, acc[r][3]);
                }
            }
        }
    }
    __syncthreads();   // qsm/kT reads done; S may overwrite

    // ---- register softmax + store expS (unnormalized), keep inv[] in regs ----
    float inv[7];
    {
        const int c1 = 4 * tj + 32;
        #pragma unroll
        for (int r = 0; r < 7; r++) {
            float s0, s1, s2, s3, s4, s5, s6, s7;
            unpack2(acc[r][0], s0, s1);
            unpack2(acc[r][1], s2, s3);
            unpack2(acc[r][2], s4, s5);
            unpack2(acc[r][3], s6, s7);
            if (c1     >= 49) s4 = -1e30f;
            if (c1 + 1 >= 49) s5 = -1e30f;
            if (c1 + 2 >= 49) s6 = -1e30f;
            if (c1 + 3 >= 49) s7 = -1e30f;
            float m = fmaxf(fmaxf(fmaxf(s0, s1), fmaxf(s2, s3)),
                            fmaxf(fmaxf(s4, s5), fmaxf(s6, s7)));
            m = fmaxf(m, __shfl_xor_sync(0xffffffffu, m, 1));
            m = fmaxf(m, __shfl_xor_sync(0xffffffffu, m, 2));
            m = fmaxf(m, __shfl_xor_sync(0xffffffffu, m, 4));
            float e0 = __expf(s0 - m), e1 = __expf(s1 - m);
            float e2 = __expf(s2 - m), e3 = __expf(s3 - m);
            float e4 = __expf(s4 - m), e5 = __expf(s5 - m);
            float e6 = __expf(s6 - m), e7 = __expf(s7 - m);
            float sum = ((e0 + e1) + (e2 + e3)) + ((e4 + e5) + (e6 + e7));
            sum += __shfl_xor_sync(0xffffffffu, sum, 1);
            sum += __shfl_xor_sync(0xffffffffu, sum, 2);
            sum += __shfl_xor_sync(0xffffffffu, sum, 4);
            inv[r] = 1.f / sum;
            if (ti < 7) {
                float* srow = S + (7 * ti + r) * SS;
                *(u64*)(srow + 4 * tj)     = pack2(e0, e1);
                *(u64*)(srow + 4 * tj + 2) = pack2(e2, e3);
                if (c1 < SS) {   // tj<=4: covers cols 32..51 (invalid ones are 0)
                    *(u64*)(srow + c1)     = pack2(e4, e5);
                    *(u64*)(srow + c1 + 2) = pack2(e6, e7);
                }
            }
        }
    }
    __syncthreads();

    // ---- phase 2: out = expS @ V * inv + LePE(V) ----
    {
        u64 att[7][2], lep[7][2];
        float4 bb = *(const float4*)(bsm + tj * 4);
        u64 b01 = pack2(bb.x, bb.y), b23 = pack2(bb.z, bb.w);
        #pragma unroll
        for (int r = 0; r < 7; r++) {
            att[r][0] = 0ull; att[r][1] = 0ull;
            lep[r][0] = b01;  lep[r][1] = b23;
        }

        // LePE
        #pragma unroll
        for (int ky = 0; ky < 3; ky++) {
            int ny = ti + ky - 1;
            if (ny >= 0 && ny <= 6) {
                #pragma unroll
                for (int kx = 0; kx < 3; kx++) {
                    const ulonglong2 w2 =
                        *(const ulonglong2*)(wsm + (ky * 3 + kx) * 32 + tj * 4);
                    #pragma unroll
                    for (int r = 0; r < 7; r++) {
                        int nx = r + kx - 1;
                        if (nx >= 0 && nx <= 6) {
                            ulonglong2 v2 =
                                *(const ulonglong2*)(vsm + (ny * 7 + nx) * QVS + tj * 4);
                            lep[r][0] = ffma2(w2.x, v2.x, lep[r][0]);
                            lep[r][1] = ffma2(w2.y, v2.y, lep[r][1]);
                        }
                    }
                }
            }
        }

        // attention: k in groups of 4, float4 S reads (cols 49..51 are zero)
        const float* Sb = S + (7 * ti) * SS;
        #pragma unroll
        for (int kg = 0; kg < 13; kg++) {
            float4 s4[7];
            #pragma unroll
            for (int r = 0; r < 7; r++)
                s4[r] = *(const float4*)(Sb + r * SS + 4 * kg);
            #pragma unroll
            for (int kk = 0; kk < 4; kk++) {
                ulonglong2 v2 =
                    *(const ulonglong2*)(vsm + (4 * kg + kk) * QVS + (tj << 2));
                #pragma unroll
                for (int r = 0; r < 7; r++) {
                    float p = (kk == 0) ? s4[r].x : (kk == 1) ? s4[r].y
                            : (kk == 2) ? s4[r].z : s4[r].w;
                    u64 p2 = pack2(p, p);
                    att[r][0] = ffma2(p2, v2.x, att[r][0]);
                    att[r][1] = ffma2(p2, v2.y, att[r][1]);
                }
            }
        }

        if (ti < 7) {
            #pragma unroll
            for (int r = 0; r < 7; r++) {
                float a0, a1, a2, a3, l0, l1, l2, l3;
                unpack2(att[r][0], a0, a1); unpack2(att[r][1], a2, a3);
                unpack2(lep[r][0], l0, l1); unpack2(lep[r][1], l2, l3);
                float4 o;
                o.x = a0 * inv[r] + l0;
                o.y = a1 * inv[r] + l1;
                o.z = a2 * inv[r] + l2;
                o.w = a3 * inv[r] + l3;
                *(float4*)(out + (size_t)(tok0 + ti * 112 + r) * 384 + cbase + tj * 4) = o;
            }
        }
    }
}

extern "C" void kernel_launch(void* const* d_in, const int* in_sizes, int n_in,
                              void* d_out, int out_size)
{
    const float* qkv = (const float*)d_in[0];
    const float* cw  = (const float*)d_in[1];
    const float* cb  = (const float*)d_in[2];
    float* o = (float*)d_out;
    dim3 grid(4096, 12, 1);
    la_kernel<<<grid, 64>>>(qkv, cw, cb, o);
}